// round 5
// baseline (speedup 1.0000x reference)
#include <cuda_runtime.h>
#include <math.h>

#define B_SZ 1024
#define C_SZ 256
#define DF   512
#define DT   512
#define NHID 32

// Scratch (allocation-free: __device__ globals)
__device__ float g_Qk[B_SZ * DF];     // Q @ Wk_w  [b][f]
__device__ float g_r[B_SZ * DF];      // softmax-weighted feature read [b][f]
__device__ float g_scale[B_SZ];       // mean |features| per b
__device__ float g_gate[B_SZ];        // sigmoid gate per b

// ---------------------------------------------------------------------------
// cp.async helpers
// ---------------------------------------------------------------------------
__device__ __forceinline__ void cp_async16(float* dst, const float* src) {
    unsigned s = (unsigned)__cvta_generic_to_shared(dst);
    asm volatile("cp.async.cg.shared.global [%0], [%1], 16;\n" :: "r"(s), "l"(src) : "memory");
}
__device__ __forceinline__ void issue_chunk(float* dst, const float* src, int tid) {
    // 32 channels x 512 floats = 4096 float4; 512 threads -> 8 each
    #pragma unroll
    for (int i = 0; i < 8; i++)
        cp_async16(dst + 4 * (tid + i * 512), src + 4 * (tid + i * 512));
    asm volatile("cp.async.commit_group;\n" ::: "memory");
}

// ---------------------------------------------------------------------------
// Kernel 1: Qk[b][f] = sum_t Q[b][t] * Wk[t][f]
// Tile: 32 b x 128 f, K-step 32, 256 threads, 4x4 register tile per thread.
// ---------------------------------------------------------------------------
__global__ __launch_bounds__(256) void qk_gemm(const float* __restrict__ Q,
                                               const float* __restrict__ Wk) {
    __shared__ float As[32 * 36];   // As[kk][b] (transposed, stride 36)
    __shared__ float Bs[32 * 128];  // Bs[kk][f]
    const int tid  = threadIdx.x;
    const int b0   = blockIdx.y * 32;
    const int f0   = blockIdx.x * 128;
    const int bq   = tid >> 5;      // 0..7  (warp id)
    const int lane = tid & 31;
    float acc[4][4] = {};

    for (int k0 = 0; k0 < DT; k0 += 32) {
        __syncthreads();
        {   // A tile: 32 b x 32 k, transpose-store
            int brow = tid >> 3;
            int kc   = (tid & 7) * 4;
            float4 v = *(const float4*)(Q + (size_t)(b0 + brow) * DT + k0 + kc);
            As[(kc + 0) * 36 + brow] = v.x;
            As[(kc + 1) * 36 + brow] = v.y;
            As[(kc + 2) * 36 + brow] = v.z;
            As[(kc + 3) * 36 + brow] = v.w;
        }
        {   // B tile: 32 k x 128 f (f contiguous, coalesced)
            int kr = tid >> 5;
            #pragma unroll
            for (int p = 0; p < 4; p++) {
                int kk = kr + p * 8;
                float4 v = *(const float4*)(Wk + (size_t)(k0 + kk) * DF + f0 + lane * 4);
                *(float4*)(Bs + kk * 128 + lane * 4) = v;
            }
        }
        __syncthreads();
        #pragma unroll
        for (int kk = 0; kk < 32; kk++) {
            float4 a = *(const float4*)(As + kk * 36 + bq * 4);
            float4 w = *(const float4*)(Bs + kk * 128 + lane * 4);
            acc[0][0] = fmaf(a.x, w.x, acc[0][0]); acc[0][1] = fmaf(a.x, w.y, acc[0][1]);
            acc[0][2] = fmaf(a.x, w.z, acc[0][2]); acc[0][3] = fmaf(a.x, w.w, acc[0][3]);
            acc[1][0] = fmaf(a.y, w.x, acc[1][0]); acc[1][1] = fmaf(a.y, w.y, acc[1][1]);
            acc[1][2] = fmaf(a.y, w.z, acc[1][2]); acc[1][3] = fmaf(a.y, w.w, acc[1][3]);
            acc[2][0] = fmaf(a.z, w.x, acc[2][0]); acc[2][1] = fmaf(a.z, w.y, acc[2][1]);
            acc[2][2] = fmaf(a.z, w.z, acc[2][2]); acc[2][3] = fmaf(a.z, w.w, acc[2][3]);
            acc[3][0] = fmaf(a.w, w.x, acc[3][0]); acc[3][1] = fmaf(a.w, w.y, acc[3][1]);
            acc[3][2] = fmaf(a.w, w.z, acc[3][2]); acc[3][3] = fmaf(a.w, w.w, acc[3][3]);
        }
    }
    #pragma unroll
    for (int i = 0; i < 4; i++) {
        float4 v = make_float4(acc[i][0], acc[i][1], acc[i][2], acc[i][3]);
        *(float4*)(g_Qk + (size_t)(b0 + bq * 4 + i) * DF + f0 + lane * 4) = v;
    }
}

// ---------------------------------------------------------------------------
// Kernel 2: per-batch online-softmax attention over features, single HBM pass.
// One CTA per b, 512 threads. Chunks of 32 channels, double-buffered cp.async.
// Produces g_r[b][f] and g_scale[b].
// ---------------------------------------------------------------------------
__global__ __launch_bounds__(512) void attn_kernel(const float* __restrict__ feat) {
    extern __shared__ float sm[];
    float* Qks  = sm;                    // 512
    float* buf  = sm + 512;              // 2 * 32 * 512 = 32768
    float* pb   = buf + 2 * 32 * DF;     // 32 exp-probs
    float* sc   = pb + 32;               // 32 scores / later warp abs sums
    float* sred = sc + 32;               // [0]=alpha, [1]=l

    const int b    = blockIdx.x;
    const int tid  = threadIdx.x;
    const int lane = tid & 31;
    const int wid  = tid >> 5;
    const float* Fb = feat + (size_t)b * C_SZ * DF;

    Qks[tid] = g_Qk[(size_t)b * DF + tid];

    // prologue: two chunks in flight
    issue_chunk(buf + 0 * 32 * DF, Fb + 0 * 32 * DF, tid);
    issue_chunk(buf + 1 * 32 * DF, Fb + 1 * 32 * DF, tid);
    __syncthreads();

    const float inv_sqrt_d = 0.044194173824159216f; // 1/sqrt(512)
    float qreg[16];
    #pragma unroll
    for (int k = 0; k < 16; k++) qreg[k] = Qks[lane + 32 * k] * inv_sqrt_d;

    float acc = 0.f;          // this thread owns feature index f = tid
    float m = -INFINITY;      // tracked meaningfully by warp 0
    float l = 0.f;            // tracked by tid 0
    float wabs = 0.f;         // per-warp |f| accumulator (lane 0)

    for (int ch = 0; ch < 8; ch++) {
        const int bi = ch & 1;
        if (ch < 7) asm volatile("cp.async.wait_group 1;\n" ::: "memory");
        else        asm volatile("cp.async.wait_group 0;\n" ::: "memory");
        __syncthreads();
        float* Bp = buf + bi * 32 * DF;

        // scores: warp w handles channels 2w, 2w+1
        #pragma unroll
        for (int cc = 0; cc < 2; cc++) {
            int c = wid * 2 + cc;
            const float* row = Bp + c * DF;
            float s = 0.f, a = 0.f;
            #pragma unroll
            for (int k = 0; k < 16; k++) {
                float v = row[lane + 32 * k];
                s = fmaf(qreg[k], v, s);
                a += fabsf(v);
            }
            #pragma unroll
            for (int o = 16; o; o >>= 1) {
                s += __shfl_xor_sync(0xffffffffu, s, o);
                a += __shfl_xor_sync(0xffffffffu, a, o);
            }
            if (lane == 0) { sc[c] = s; wabs += a; }
        }
        __syncthreads();

        // warp 0: chunk max, exp weights, running (m, l)
        if (wid == 0) {
            float s  = sc[lane];
            float cm = s;
            #pragma unroll
            for (int o = 16; o; o >>= 1) cm = fmaxf(cm, __shfl_xor_sync(0xffffffffu, cm, o));
            float mn    = fmaxf(m, cm);
            float alpha = __expf(m - mn);
            float p     = __expf(s - mn);
            m = mn;
            pb[lane] = p;
            float ps = p;
            #pragma unroll
            for (int o = 16; o; o >>= 1) ps += __shfl_xor_sync(0xffffffffu, ps, o);
            if (lane == 0) { l = l * alpha + ps; sred[0] = alpha; }
        }
        __syncthreads();

        // weighted accumulation: acc_f = acc_f*alpha + sum_c p_c * F[c][f]
        float alpha = sred[0];
        float an = acc * alpha;
        #pragma unroll
        for (int c = 0; c < 32; c++) an = fmaf(pb[c], Bp[c * DF + tid], an);
        acc = an;
        __syncthreads();   // everyone done reading Bp before overwrite

        if (ch + 2 < 8) issue_chunk(buf + bi * 32 * DF, Fb + (ch + 2) * 32 * DF, tid);
    }

    if (tid == 0)  sred[1] = l;
    if (lane == 0) sc[wid] = wabs;
    __syncthreads();

    float linv = 1.0f / sred[1];
    g_r[(size_t)b * DF + tid] = acc * linv;

    if (tid == 0) {
        float t = 0.f;
        #pragma unroll
        for (int w = 0; w < 16; w++) t += sc[w];
        g_scale[b] = t * (1.0f / (float)(C_SZ * DF));
    }
}

// ---------------------------------------------------------------------------
// Kernel 3: gate MLP. One warp per b.
// gate = sigmoid(g2 . gelu(g1 @ [Q_b, scale_b] + g1_b) + g2_b)
// ---------------------------------------------------------------------------
__global__ __launch_bounds__(128) void gate_kernel(const float* __restrict__ Q,
                                                   const float* __restrict__ g1w,
                                                   const float* __restrict__ g1b,
                                                   const float* __restrict__ g2w,
                                                   const float* __restrict__ g2b,
                                                   float* __restrict__ gate_out) {
    const int w    = threadIdx.x >> 5;
    const int lane = threadIdx.x & 31;
    const int b    = blockIdx.x * 4 + w;
    const float* q   = Q + (size_t)b * DT;
    const float* row = g1w + lane * (DT + 1);   // HID=32 rows, lane = hidden unit

    float h = g1b[lane];
    #pragma unroll 4
    for (int d = 0; d < DT; d++) h = fmaf(q[d], row[d], h);
    h = fmaf(g_scale[b], row[DT], h);

    // exact gelu: x * 0.5 * (1 + erf(x/sqrt(2)))
    float ge = 0.5f * h * (1.0f + erff(h * 0.70710678118654752f));
    float y  = g2w[lane] * ge;
    #pragma unroll
    for (int o = 16; o; o >>= 1) y += __shfl_xor_sync(0xffffffffu, y, o);

    if (lane == 0) {
        float gate = 1.0f / (1.0f + expf(-(y + g2b[0])));
        g_gate[b]   = gate;
        gate_out[b] = gate;
    }
}

// ---------------------------------------------------------------------------
// Kernel 4: out[b][t] = gate[b] * ( sum_f r[b][f]*Wv[t][f] + Wv_b[t] )
// NT GEMM (k = f contiguous in both operands). Tile 32 b x 128 t, K-step 32.
// ---------------------------------------------------------------------------
__global__ __launch_bounds__(256) void out_gemm(const float* __restrict__ Wv,
                                                const float* __restrict__ Wvb,
                                                float* __restrict__ out) {
    __shared__ float As[32 * 36];    // As[kk][b]
    __shared__ float Bs[32 * 132];   // Bs[kk][t] (transposed Wv tile)
    const int tid  = threadIdx.x;
    const int b0   = blockIdx.y * 32;
    const int t0   = blockIdx.x * 128;
    const int bq   = tid >> 5;
    const int lane = tid & 31;
    float acc[4][4] = {};

    for (int k0 = 0; k0 < DF; k0 += 32) {
        __syncthreads();
        {   // A tile: r[b][f] 32x32, transpose-store
            int brow = tid >> 3;
            int kc   = (tid & 7) * 4;
            float4 v = *(const float4*)(g_r + (size_t)(b0 + brow) * DF + k0 + kc);
            As[(kc + 0) * 36 + brow] = v.x;
            As[(kc + 1) * 36 + brow] = v.y;
            As[(kc + 2) * 36 + brow] = v.z;
            As[(kc + 3) * 36 + brow] = v.w;
        }
        {   // B tile: Wv[t][f] 128t x 32f, transpose-store (coalesced along f)
            int fc = (tid & 7) * 4;
            #pragma unroll
            for (int p = 0; p < 4; p++) {
                int trow = (tid >> 3) + 32 * p;
                float4 v = *(const float4*)(Wv + (size_t)(t0 + trow) * DF + k0 + fc);
                Bs[(fc + 0) * 132 + trow] = v.x;
                Bs[(fc + 1) * 132 + trow] = v.y;
                Bs[(fc + 2) * 132 + trow] = v.z;
                Bs[(fc + 3) * 132 + trow] = v.w;
            }
        }
        __syncthreads();
        #pragma unroll
        for (int kk = 0; kk < 32; kk++) {
            float4 a = *(const float4*)(As + kk * 36 + bq * 4);
            float4 w = *(const float4*)(Bs + kk * 132 + lane * 4);
            acc[0][0] = fmaf(a.x, w.x, acc[0][0]); acc[0][1] = fmaf(a.x, w.y, acc[0][1]);
            acc[0][2] = fmaf(a.x, w.z, acc[0][2]); acc[0][3] = fmaf(a.x, w.w, acc[0][3]);
            acc[1][0] = fmaf(a.y, w.x, acc[1][0]); acc[1][1] = fmaf(a.y, w.y, acc[1][1]);
            acc[1][2] = fmaf(a.y, w.z, acc[1][2]); acc[1][3] = fmaf(a.y, w.w, acc[1][3]);
            acc[2][0] = fmaf(a.z, w.x, acc[2][0]); acc[2][1] = fmaf(a.z, w.y, acc[2][1]);
            acc[2][2] = fmaf(a.z, w.z, acc[2][2]); acc[2][3] = fmaf(a.z, w.w, acc[2][3]);
            acc[3][0] = fmaf(a.w, w.x, acc[3][0]); acc[3][1] = fmaf(a.w, w.y, acc[3][1]);
            acc[3][2] = fmaf(a.w, w.z, acc[3][2]); acc[3][3] = fmaf(a.w, w.w, acc[3][3]);
        }
    }

    float4 bias = *(const float4*)(Wvb + t0 + lane * 4);
    #pragma unroll
    for (int i = 0; i < 4; i++) {
        int b  = b0 + bq * 4 + i;
        float g = g_gate[b];
        float4 v;
        v.x = g * (acc[i][0] + bias.x);
        v.y = g * (acc[i][1] + bias.y);
        v.z = g * (acc[i][2] + bias.z);
        v.w = g * (acc[i][3] + bias.w);
        *(float4*)(out + (size_t)b * DT + t0 + lane * 4) = v;
    }
}

// ---------------------------------------------------------------------------
// Launch. Inputs (metadata order): Q, features, Wk_w, Wk_b, Wv_w, Wv_b,
// g1_w, g1_b, g2_w, g2_b. Output: [gate*feat_read (1024x512), gate (1024)].
// Note: Wk_b shifts all scores of a batch equally -> cancels in softmax.
// ---------------------------------------------------------------------------
extern "C" void kernel_launch(void* const* d_in, const int* in_sizes, int n_in,
                              void* d_out, int out_size) {
    const float* Q   = (const float*)d_in[0];
    const float* F   = (const float*)d_in[1];
    const float* Wk  = (const float*)d_in[2];
    const float* Wvw = (const float*)d_in[4];
    const float* Wvb = (const float*)d_in[5];
    const float* g1w = (const float*)d_in[6];
    const float* g1b = (const float*)d_in[7];
    const float* g2w = (const float*)d_in[8];
    const float* g2b = (const float*)d_in[9];
    float* out = (float*)d_out;

    const int attn_smem = (512 + 2 * 32 * DF + 32 + 32 + 8) * (int)sizeof(float); // 133408 B
    cudaFuncSetAttribute(attn_kernel, cudaFuncAttributeMaxDynamicSharedMemorySize, attn_smem);

    qk_gemm<<<dim3(4, 32), 256>>>(Q, Wk);
    attn_kernel<<<B_SZ, 512, attn_smem>>>(F);
    gate_kernel<<<B_SZ / 4, 128>>>(Q, g1w, g1b, g2w, g2b, out + B_SZ * DT);
    out_gemm<<<dim3(4, 32), 256>>>(Wvw, Wvb, out);
}

// round 7
// speedup vs baseline: 1.3424x; 1.3424x over previous
#include <cuda_runtime.h>
#include <math.h>

#define B_SZ 1024
#define C_SZ 256
#define DF   512
#define DT   512
#define NHID 32

// Scratch (allocation-free: __device__ globals)
__device__ float g_Qk[B_SZ * DF];        // Q @ Wk_w  [b][f]
__device__ float g_r[B_SZ * DF];         // softmax-weighted feature read [b][f]
__device__ float g_scale[B_SZ];          // mean |features| per b
__device__ float g_gate[B_SZ];           // sigmoid gate per b
__device__ float g_w1t[(DT + 1) * NHID]; // g1_w transposed: [d][h]

// ---------------------------------------------------------------------------
// helpers
// ---------------------------------------------------------------------------
__device__ __forceinline__ void cp_async16(float* dst, const float* src) {
    unsigned s = (unsigned)__cvta_generic_to_shared(dst);
    asm volatile("cp.async.cg.shared.global [%0], [%1], 16;\n" :: "r"(s), "l"(src) : "memory");
}
__device__ __forceinline__ unsigned long long pack2(float x) {
    unsigned long long r;
    asm("mov.b64 %0, {%1, %1};" : "=l"(r) : "r"(__float_as_uint(x)));
    return r;
}
__device__ __forceinline__ void ffma2(unsigned long long& acc, unsigned long long a,
                                      unsigned long long w) {
    asm("fma.rn.f32x2 %0, %1, %2, %0;" : "+l"(acc) : "l"(a), "l"(w));
}
__device__ __forceinline__ float lo32(unsigned long long v) {
    return __uint_as_float((unsigned)v);
}
__device__ __forceinline__ float hi32(unsigned long long v) {
    return __uint_as_float((unsigned)(v >> 32));
}

// ---------------------------------------------------------------------------
// Kernel 0: transpose g1_w [32][513] -> g_w1t [513][32]
// ---------------------------------------------------------------------------
__global__ void transpose_w1(const float* __restrict__ g1w) {
    int i = blockIdx.x * 256 + threadIdx.x;
    if (i < (DT + 1) * NHID) {
        int d = i >> 5, h = i & 31;
        g_w1t[i] = g1w[h * (DT + 1) + d];
    }
}

// ---------------------------------------------------------------------------
// Kernel 1: Qk[b][f] = sum_t Q[b][t] * Wk[t][f]
// Tile 32b x 128f, K-step 32, 256 threads, 4x4 per thread (f32x2 packed).
// A (Q, [b][k]) -> LDG + transposed STS, reg-staged.  B (Wk, [k][f]) -> cp.async.
// Double-buffered smem, 2 syncs/iter.
// ---------------------------------------------------------------------------
__global__ __launch_bounds__(256) void qk_gemm(const float* __restrict__ Q,
                                               const float* __restrict__ Wk) {
    __shared__ float As[2][32 * 36];   // [k][b], stride 36
    __shared__ float Bs[2][32 * 128];  // [k][f]
    const int tid  = threadIdx.x;
    const int b0   = blockIdx.y * 32;
    const int f0   = blockIdx.x * 128;
    const int wq   = tid >> 5;
    const int lane = tid & 31;
    const int brow = tid >> 3;
    const int kc   = (tid & 7) * 4;
    const int kr   = tid >> 5;

    unsigned long long acc[4][2] = {};

    // prologue: tile 0
    float4 rA = *(const float4*)(Q + (size_t)(b0 + brow) * DT + kc);
    #pragma unroll
    for (int p = 0; p < 4; p++) {
        int kk = kr + p * 8;
        cp_async16(&Bs[0][kk * 128 + lane * 4], Wk + (size_t)kk * DF + f0 + lane * 4);
    }
    asm volatile("cp.async.commit_group;\n" ::: "memory");

    #pragma unroll 1
    for (int it = 0; it < 16; it++) {
        const int cur = it & 1, nxt = cur ^ 1;
        // store staged A tile (transposed)
        As[cur][(kc + 0) * 36 + brow] = rA.x;
        As[cur][(kc + 1) * 36 + brow] = rA.y;
        As[cur][(kc + 2) * 36 + brow] = rA.z;
        As[cur][(kc + 3) * 36 + brow] = rA.w;
        if (it < 15) {
            const int k0n = (it + 1) * 32;
            rA = *(const float4*)(Q + (size_t)(b0 + brow) * DT + k0n + kc);
            #pragma unroll
            for (int p = 0; p < 4; p++) {
                int kk = kr + p * 8;
                cp_async16(&Bs[nxt][kk * 128 + lane * 4],
                           Wk + (size_t)(k0n + kk) * DF + f0 + lane * 4);
            }
            asm volatile("cp.async.commit_group;\n" ::: "memory");
            asm volatile("cp.async.wait_group 1;\n" ::: "memory");
        } else {
            asm volatile("cp.async.wait_group 0;\n" ::: "memory");
        }
        __syncthreads();
        #pragma unroll
        for (int kk = 0; kk < 32; kk++) {
            float4 a4 = *(const float4*)(&As[cur][kk * 36 + wq * 4]);
            ulonglong2 w = *(const ulonglong2*)(&Bs[cur][kk * 128 + lane * 4]);
            unsigned long long a0 = pack2(a4.x), a1 = pack2(a4.y),
                               a2 = pack2(a4.z), a3 = pack2(a4.w);
            ffma2(acc[0][0], a0, w.x); ffma2(acc[0][1], a0, w.y);
            ffma2(acc[1][0], a1, w.x); ffma2(acc[1][1], a1, w.y);
            ffma2(acc[2][0], a2, w.x); ffma2(acc[2][1], a2, w.y);
            ffma2(acc[3][0], a3, w.x); ffma2(acc[3][1], a3, w.y);
        }
        __syncthreads();
    }
    #pragma unroll
    for (int i = 0; i < 4; i++) {
        float4 v = make_float4(lo32(acc[i][0]), hi32(acc[i][0]),
                               lo32(acc[i][1]), hi32(acc[i][1]));
        *(float4*)(g_Qk + (size_t)(b0 + wq * 4 + i) * DF + f0 + lane * 4) = v;
    }
}

// ---------------------------------------------------------------------------
// Kernel 2: per-batch online-softmax attention over features, single HBM pass.
// One CTA per b, 512 threads. 16-channel chunks, 3-stage cp.async pipeline
// (~100KB smem -> 2 CTAs/SM). Produces g_r[b][f] and g_scale[b].
// ---------------------------------------------------------------------------
__global__ __launch_bounds__(512) void attn_kernel(const float* __restrict__ feat) {
    extern __shared__ float sm[];
    float* Qks  = sm;                     // 512
    float* buf  = sm + 512;               // 3 * 16 * 512 = 24576
    float* pb   = buf + 3 * 16 * DF;      // 16 exp-probs
    float* sc   = pb + 16;                // 16 scores / later warp abs sums
    float* sred = sc + 32;                // [0]=alpha, [1]=l

    const int b    = blockIdx.x;
    const int tid  = threadIdx.x;
    const int lane = tid & 31;
    const int wid  = tid >> 5;
    const float* Fb = feat + (size_t)b * C_SZ * DF;

    Qks[tid] = g_Qk[(size_t)b * DF + tid];

    // prologue: three 16-channel chunks in flight (16*512 floats = 2048 f4, 4/thread)
    #pragma unroll
    for (int s = 0; s < 3; s++) {
        float* dst = buf + s * 16 * DF;
        const float* src = Fb + (size_t)s * 16 * DF;
        #pragma unroll
        for (int i = 0; i < 4; i++)
            cp_async16(dst + 4 * (tid + i * 512), src + 4 * (tid + i * 512));
        asm volatile("cp.async.commit_group;\n" ::: "memory");
    }
    __syncthreads();

    const float inv_sqrt_d = 0.044194173824159216f; // 1/sqrt(512)
    float qreg[16];
    #pragma unroll
    for (int k = 0; k < 16; k++) qreg[k] = Qks[lane + 32 * k] * inv_sqrt_d;

    float acc = 0.f;        // this thread owns feature index f = tid
    float m = -INFINITY;    // warp 0
    float l = 0.f;          // tid 0
    float wabs = 0.f;       // per-warp |f| accumulator (lane 0)

    #pragma unroll 1
    for (int ch = 0; ch < 16; ch++) {
        if (ch <= 13)      asm volatile("cp.async.wait_group 2;\n" ::: "memory");
        else if (ch == 14) asm volatile("cp.async.wait_group 1;\n" ::: "memory");
        else               asm volatile("cp.async.wait_group 0;\n" ::: "memory");
        __syncthreads();
        float* Bp = buf + (ch % 3) * 16 * DF;

        // scores: warp w handles channel w (16 warps, 16 channels)
        {
            const float* row = Bp + wid * DF;
            float s = 0.f, a = 0.f;
            #pragma unroll
            for (int k = 0; k < 16; k++) {
                float v = row[lane + 32 * k];
                s = fmaf(qreg[k], v, s);
                a += fabsf(v);
            }
            #pragma unroll
            for (int o = 16; o; o >>= 1) {
                s += __shfl_xor_sync(0xffffffffu, s, o);
                a += __shfl_xor_sync(0xffffffffu, a, o);
            }
            if (lane == 0) { sc[wid] = s; wabs += a; }
        }
        __syncthreads();

        // warp 0: chunk max, exp weights, running (m, l)
        if (wid == 0) {
            float s  = (lane < 16) ? sc[lane] : -INFINITY;
            float cm = s;
            #pragma unroll
            for (int o = 16; o; o >>= 1) cm = fmaxf(cm, __shfl_xor_sync(0xffffffffu, cm, o));
            float mn    = fmaxf(m, cm);
            float alpha = __expf(m - mn);
            float p     = (lane < 16) ? __expf(s - mn) : 0.f;
            m = mn;
            if (lane < 16) pb[lane] = p;
            float ps = p;
            #pragma unroll
            for (int o = 16; o; o >>= 1) ps += __shfl_xor_sync(0xffffffffu, ps, o);
            if (lane == 0) { l = l * alpha + ps; sred[0] = alpha; }
        }
        __syncthreads();

        // weighted accumulation
        float alpha = sred[0];
        float an = acc * alpha;
        #pragma unroll
        for (int c = 0; c < 16; c++) an = fmaf(pb[c], Bp[c * DF + tid], an);
        acc = an;
        __syncthreads();   // all done reading Bp before reissue into it

        if (ch + 3 < 16) {
            float* dst = buf + (ch % 3) * 16 * DF;
            const float* src = Fb + (size_t)(ch + 3) * 16 * DF;
            #pragma unroll
            for (int i = 0; i < 4; i++)
                cp_async16(dst + 4 * (tid + i * 512), src + 4 * (tid + i * 512));
            asm volatile("cp.async.commit_group;\n" ::: "memory");
        }
    }

    if (tid == 0)  sred[1] = l;
    if (lane == 0) sc[wid] = wabs;
    __syncthreads();

    float linv = 1.0f / sred[1];
    g_r[(size_t)b * DF + tid] = acc * linv;

    if (tid == 0) {
        float t = 0.f;
        #pragma unroll
        for (int w = 0; w < 16; w++) t += sc[w];
        g_scale[b] = t * (1.0f / (float)(C_SZ * DF));
    }
}

// ---------------------------------------------------------------------------
// Kernel 3: gate MLP with transposed g1 weights (coalesced). 8 b per block.
// gate = sigmoid(g2 . gelu(w1 @ [Q_b, scale_b] + g1_b) + g2_b)
// ---------------------------------------------------------------------------
__global__ __launch_bounds__(256) void gate_kernel(const float* __restrict__ Q,
                                                   const float* __restrict__ g1b,
                                                   const float* __restrict__ g2w,
                                                   const float* __restrict__ g2b,
                                                   float* __restrict__ gate_out) {
    __shared__ float qs[8 * DT];
    const int tid  = threadIdx.x;
    const int b0   = blockIdx.x * 8;
    const int w    = tid >> 5;
    const int lane = tid & 31;

    #pragma unroll
    for (int i = 0; i < 4; i++) {
        int j = tid + i * 256;
        *(float4*)(qs + 4 * j) = *(const float4*)(Q + (size_t)b0 * DT + 4 * j);
    }
    __syncthreads();

    const int b = b0 + w;
    float h = g1b[lane];
    const float* qrow = qs + w * DT;
    #pragma unroll 8
    for (int d = 0; d < DT; d++)
        h = fmaf(qrow[d], g_w1t[d * NHID + lane], h);
    h = fmaf(g_scale[b], g_w1t[DT * NHID + lane], h);

    float ge = 0.5f * h * (1.0f + erff(h * 0.70710678118654752f));
    float y  = g2w[lane] * ge;
    #pragma unroll
    for (int o = 16; o; o >>= 1) y += __shfl_xor_sync(0xffffffffu, y, o);

    if (lane == 0) {
        float gate = 1.0f / (1.0f + expf(-(y + g2b[0])));
        g_gate[b]   = gate;
        gate_out[b] = gate;
    }
}

// ---------------------------------------------------------------------------
// Kernel 4: out[b][t] = gate[b] * ( sum_f r[b][f]*Wv[t][f] + Wv_b[t] )
// NT GEMM. Tile 32b x 128t, K-step 32, 256 threads, f32x2 inner.
// Both operands K-contiguous -> both LDG + transposed STS, reg-staged,
// double-buffered smem.
// ---------------------------------------------------------------------------
__global__ __launch_bounds__(256) void out_gemm(const float* __restrict__ Wv,
                                                const float* __restrict__ Wvb,
                                                float* __restrict__ out) {
    __shared__ float As[2][32 * 36];    // [f][b], stride 36
    __shared__ float Bs[2][32 * 132];   // [f][t], stride 132
    const int tid  = threadIdx.x;
    const int b0   = blockIdx.y * 32;
    const int t0   = blockIdx.x * 128;
    const int wq   = tid >> 5;
    const int lane = tid & 31;
    const int arow = tid >> 3;          // 0..31 (b for A, t-subrow for B)
    const int kc   = (tid & 7) * 4;

    unsigned long long acc[4][2] = {};

    // prologue: tile 0
    float4 rA = *(const float4*)(g_r + (size_t)(b0 + arow) * DF + kc);
    float4 rB[4];
    #pragma unroll
    for (int p = 0; p < 4; p++)
        rB[p] = *(const float4*)(Wv + (size_t)(t0 + arow + 32 * p) * DF + kc);

    #pragma unroll 1
    for (int it = 0; it < 16; it++) {
        const int cur = it & 1;
        As[cur][(kc + 0) * 36 + arow] = rA.x;
        As[cur][(kc + 1) * 36 + arow] = rA.y;
        As[cur][(kc + 2) * 36 + arow] = rA.z;
        As[cur][(kc + 3) * 36 + arow] = rA.w;
        #pragma unroll
        for (int p = 0; p < 4; p++) {
            int tr = arow + 32 * p;
            Bs[cur][(kc + 0) * 132 + tr] = rB[p].x;
            Bs[cur][(kc + 1) * 132 + tr] = rB[p].y;
            Bs[cur][(kc + 2) * 132 + tr] = rB[p].z;
            Bs[cur][(kc + 3) * 132 + tr] = rB[p].w;
        }
        if (it < 15) {
            const int k0n = (it + 1) * 32;
            rA = *(const float4*)(g_r + (size_t)(b0 + arow) * DF + k0n + kc);
            #pragma unroll
            for (int p = 0; p < 4; p++)
                rB[p] = *(const float4*)(Wv + (size_t)(t0 + arow + 32 * p) * DF + k0n + kc);
        }
        __syncthreads();
        #pragma unroll
        for (int kk = 0; kk < 32; kk++) {
            float4 a4 = *(const float4*)(&As[cur][kk * 36 + wq * 4]);
            ulonglong2 w = *(const ulonglong2*)(&Bs[cur][kk * 132 + lane * 4]);
            unsigned long long a0 = pack2(a4.x), a1 = pack2(a4.y),
                               a2 = pack2(a4.z), a3 = pack2(a4.w);
            ffma2(acc[0][0], a0, w.x); ffma2(acc[0][1], a0, w.y);
            ffma2(acc[1][0], a1, w.x); ffma2(acc[1][1], a1, w.y);
            ffma2(acc[2][0], a2, w.x); ffma2(acc[2][1], a2, w.y);
            ffma2(acc[3][0], a3, w.x); ffma2(acc[3][1], a3, w.y);
        }
        __syncthreads();
    }

    float4 bias = *(const float4*)(Wvb + t0 + lane * 4);
    #pragma unroll
    for (int i = 0; i < 4; i++) {
        int bb = b0 + wq * 4 + i;
        float g = g_gate[bb];
        float4 v;
        v.x = g * (lo32(acc[i][0]) + bias.x);
        v.y = g * (hi32(acc[i][0]) + bias.y);
        v.z = g * (lo32(acc[i][1]) + bias.z);
        v.w = g * (hi32(acc[i][1]) + bias.w);
        *(float4*)(out + (size_t)bb * DT + t0 + lane * 4) = v;
    }
}

// ---------------------------------------------------------------------------
// Launch. Inputs: Q, features, Wk_w, Wk_b, Wv_w, Wv_b, g1_w, g1_b, g2_w, g2_b.
// Output: [gate*feat_read (1024x512), gate (1024)].
// Wk_b shifts all scores of a batch equally -> cancels in softmax.
// ---------------------------------------------------------------------------
extern "C" void kernel_launch(void* const* d_in, const int* in_sizes, int n_in,
                              void* d_out, int out_size) {
    const float* Q   = (const float*)d_in[0];
    const float* F   = (const float*)d_in[1];
    const float* Wk  = (const float*)d_in[2];
    const float* Wvw = (const float*)d_in[4];
    const float* Wvb = (const float*)d_in[5];
    const float* g1w = (const float*)d_in[6];
    const float* g1b = (const float*)d_in[7];
    const float* g2w = (const float*)d_in[8];
    const float* g2b = (const float*)d_in[9];
    float* out = (float*)d_out;

    const int attn_smem = (512 + 3 * 16 * DF + 16 + 32 + 8) * (int)sizeof(float); // ~100.6 KB
    cudaFuncSetAttribute(attn_kernel, cudaFuncAttributeMaxDynamicSharedMemorySize, attn_smem);

    transpose_w1<<<65, 256>>>(g1w);
    qk_gemm<<<dim3(4, 32), 256>>>(Q, Wk);
    attn_kernel<<<B_SZ, 512, attn_smem>>>(F);
    gate_kernel<<<B_SZ / 8, 256>>>(Q, g1b, g2w, g2b, out + B_SZ * DT);
    out_gemm<<<dim3(4, 32), 256>>>(Wvw, Wvb, out);
}

// round 8
// speedup vs baseline: 1.5707x; 1.1701x over previous
#include <cuda_runtime.h>
#include <math.h>

#define B_SZ 1024
#define C_SZ 256
#define DF   512
#define DT   512
#define NHID 32

// Scratch (allocation-free: __device__ globals)
__device__ float g_Qk[B_SZ * DF];        // Q @ Wk_w  [b][f]
__device__ float g_r[B_SZ * DF];         // softmax-weighted feature read [b][f]
__device__ float g_gate[B_SZ];           // sigmoid gate per b

// ---------------------------------------------------------------------------
// helpers
// ---------------------------------------------------------------------------
__device__ __forceinline__ void cp_async16(float* dst, const float* src) {
    unsigned s = (unsigned)__cvta_generic_to_shared(dst);
    asm volatile("cp.async.cg.shared.global [%0], [%1], 16;\n" :: "r"(s), "l"(src) : "memory");
}
__device__ __forceinline__ unsigned long long pack2(float x) {
    unsigned long long r;
    asm("mov.b64 %0, {%1, %1};" : "=l"(r) : "r"(__float_as_uint(x)));
    return r;
}
__device__ __forceinline__ void ffma2(unsigned long long& acc, unsigned long long a,
                                      unsigned long long w) {
    asm("fma.rn.f32x2 %0, %1, %2, %0;" : "+l"(acc) : "l"(a), "l"(w));
}
__device__ __forceinline__ float lo32(unsigned long long v) {
    return __uint_as_float((unsigned)v);
}
__device__ __forceinline__ float hi32(unsigned long long v) {
    return __uint_as_float((unsigned)(v >> 32));
}

// ---------------------------------------------------------------------------
// Kernel 1: Qk[b][f] = sum_t Q[b][t] * Wk[t][f]
// Tile 32b x 128f, K-step 32, 256 threads, 4x4 per thread (f32x2 packed).
// A (Q, [b][k]) -> LDG + transposed STS, reg-staged.  B (Wk, [k][f]) -> cp.async.
// Double-buffered smem, 2 syncs/iter.
// ---------------------------------------------------------------------------
__global__ __launch_bounds__(256) void qk_gemm(const float* __restrict__ Q,
                                               const float* __restrict__ Wk) {
    __shared__ float As[2][32 * 36];   // [k][b], stride 36
    __shared__ float Bs[2][32 * 128];  // [k][f]
    const int tid  = threadIdx.x;
    const int b0   = blockIdx.y * 32;
    const int f0   = blockIdx.x * 128;
    const int wq   = tid >> 5;
    const int lane = tid & 31;
    const int brow = tid >> 3;
    const int kc   = (tid & 7) * 4;
    const int kr   = tid >> 5;

    unsigned long long acc[4][2] = {};

    float4 rA = *(const float4*)(Q + (size_t)(b0 + brow) * DT + kc);
    #pragma unroll
    for (int p = 0; p < 4; p++) {
        int kk = kr + p * 8;
        cp_async16(&Bs[0][kk * 128 + lane * 4], Wk + (size_t)kk * DF + f0 + lane * 4);
    }
    asm volatile("cp.async.commit_group;\n" ::: "memory");

    #pragma unroll 1
    for (int it = 0; it < 16; it++) {
        const int cur = it & 1, nxt = cur ^ 1;
        As[cur][(kc + 0) * 36 + brow] = rA.x;
        As[cur][(kc + 1) * 36 + brow] = rA.y;
        As[cur][(kc + 2) * 36 + brow] = rA.z;
        As[cur][(kc + 3) * 36 + brow] = rA.w;
        if (it < 15) {
            const int k0n = (it + 1) * 32;
            rA = *(const float4*)(Q + (size_t)(b0 + brow) * DT + k0n + kc);
            #pragma unroll
            for (int p = 0; p < 4; p++) {
                int kk = kr + p * 8;
                cp_async16(&Bs[nxt][kk * 128 + lane * 4],
                           Wk + (size_t)(k0n + kk) * DF + f0 + lane * 4);
            }
            asm volatile("cp.async.commit_group;\n" ::: "memory");
            asm volatile("cp.async.wait_group 1;\n" ::: "memory");
        } else {
            asm volatile("cp.async.wait_group 0;\n" ::: "memory");
        }
        __syncthreads();
        #pragma unroll
        for (int kk = 0; kk < 32; kk++) {
            float4 a4 = *(const float4*)(&As[cur][kk * 36 + wq * 4]);
            ulonglong2 w = *(const ulonglong2*)(&Bs[cur][kk * 128 + lane * 4]);
            unsigned long long a0 = pack2(a4.x), a1 = pack2(a4.y),
                               a2 = pack2(a4.z), a3 = pack2(a4.w);
            ffma2(acc[0][0], a0, w.x); ffma2(acc[0][1], a0, w.y);
            ffma2(acc[1][0], a1, w.x); ffma2(acc[1][1], a1, w.y);
            ffma2(acc[2][0], a2, w.x); ffma2(acc[2][1], a2, w.y);
            ffma2(acc[3][0], a3, w.x); ffma2(acc[3][1], a3, w.y);
        }
        __syncthreads();
    }
    #pragma unroll
    for (int i = 0; i < 4; i++) {
        float4 v = make_float4(lo32(acc[i][0]), hi32(acc[i][0]),
                               lo32(acc[i][1]), hi32(acc[i][1]));
        *(float4*)(g_Qk + (size_t)(b0 + wq * 4 + i) * DF + f0 + lane * 4) = v;
    }
}

// ---------------------------------------------------------------------------
// Kernel 2: per-batch online-softmax attention over features, single HBM pass,
// WITH fused gate MLP epilogue.
// One CTA per b, 512 threads. 16-channel chunks, 3-stage cp.async pipeline
// (~102.6KB smem -> 2 CTAs/SM). Produces g_r[b][f], g_gate[b], gate_out[b].
// ---------------------------------------------------------------------------
__global__ __launch_bounds__(512) void attn_kernel(const float* __restrict__ feat,
                                                   const float* __restrict__ Q,
                                                   const float* __restrict__ g1w,
                                                   const float* __restrict__ g1b,
                                                   const float* __restrict__ g2w,
                                                   const float* __restrict__ g2b,
                                                   float* __restrict__ gate_out) {
    extern __shared__ float sm[];
    float* Qks  = sm;                     // 512 (Qk row)
    float* Qs   = sm + 512;               // 512 (raw Q row, for gate)
    float* buf  = Qs + 512;               // 3 * 16 * 512 = 24576
    float* pb   = buf + 3 * 16 * DF;      // 16 exp-probs
    float* sc   = pb + 16;                // 16 scores / warp abs sums / 32 hidden pre-acts
    float* sred = sc + 32;                // [0]=alpha, [1]=l, [2]=scale

    const int b    = blockIdx.x;
    const int tid  = threadIdx.x;
    const int lane = tid & 31;
    const int wid  = tid >> 5;
    const float* Fb = feat + (size_t)b * C_SZ * DF;

    Qks[tid] = g_Qk[(size_t)b * DF + tid];
    Qs[tid]  = Q[(size_t)b * DT + tid];

    // prologue: three 16-channel chunks in flight (2048 f4, 4/thread each)
    #pragma unroll
    for (int s = 0; s < 3; s++) {
        float* dst = buf + s * 16 * DF;
        const float* src = Fb + (size_t)s * 16 * DF;
        #pragma unroll
        for (int i = 0; i < 4; i++)
            cp_async16(dst + 4 * (tid + i * 512), src + 4 * (tid + i * 512));
        asm volatile("cp.async.commit_group;\n" ::: "memory");
    }
    __syncthreads();

    const float inv_sqrt_d = 0.044194173824159216f; // 1/sqrt(512)
    float qreg[16];
    #pragma unroll
    for (int k = 0; k < 16; k++) qreg[k] = Qks[lane + 32 * k] * inv_sqrt_d;

    float acc = 0.f;        // this thread owns feature index f = tid
    float m = -INFINITY;    // warp 0
    float l = 0.f;          // tid 0
    float wabs = 0.f;       // per-warp |f| accumulator (lane 0)

    #pragma unroll 1
    for (int ch = 0; ch < 16; ch++) {
        if (ch <= 13)      asm volatile("cp.async.wait_group 2;\n" ::: "memory");
        else if (ch == 14) asm volatile("cp.async.wait_group 1;\n" ::: "memory");
        else               asm volatile("cp.async.wait_group 0;\n" ::: "memory");
        __syncthreads();
        float* Bp = buf + (ch % 3) * 16 * DF;

        // scores: warp w handles channel w
        {
            const float* row = Bp + wid * DF;
            float s = 0.f, a = 0.f;
            #pragma unroll
            for (int k = 0; k < 16; k++) {
                float v = row[lane + 32 * k];
                s = fmaf(qreg[k], v, s);
                a += fabsf(v);
            }
            #pragma unroll
            for (int o = 16; o; o >>= 1) {
                s += __shfl_xor_sync(0xffffffffu, s, o);
                a += __shfl_xor_sync(0xffffffffu, a, o);
            }
            if (lane == 0) { sc[wid] = s; wabs += a; }
        }
        __syncthreads();

        // warp 0: chunk max, exp weights, running (m, l)
        if (wid == 0) {
            float s  = (lane < 16) ? sc[lane] : -INFINITY;
            float cm = s;
            #pragma unroll
            for (int o = 16; o; o >>= 1) cm = fmaxf(cm, __shfl_xor_sync(0xffffffffu, cm, o));
            float mn    = fmaxf(m, cm);
            float alpha = __expf(m - mn);
            float p     = (lane < 16) ? __expf(s - mn) : 0.f;
            m = mn;
            if (lane < 16) pb[lane] = p;
            float ps = p;
            #pragma unroll
            for (int o = 16; o; o >>= 1) ps += __shfl_xor_sync(0xffffffffu, ps, o);
            if (lane == 0) { l = l * alpha + ps; sred[0] = alpha; }
        }
        __syncthreads();

        // weighted accumulation
        float alpha = sred[0];
        float an = acc * alpha;
        #pragma unroll
        for (int c = 0; c < 16; c++) an = fmaf(pb[c], Bp[c * DF + tid], an);
        acc = an;
        __syncthreads();   // all done reading Bp before reissue into it

        if (ch + 3 < 16) {
            float* dst = buf + (ch % 3) * 16 * DF;
            const float* src = Fb + (size_t)(ch + 3) * 16 * DF;
            #pragma unroll
            for (int i = 0; i < 4; i++)
                cp_async16(dst + 4 * (tid + i * 512), src + 4 * (tid + i * 512));
            asm volatile("cp.async.commit_group;\n" ::: "memory");
        }
    }

    if (tid == 0)  sred[1] = l;
    if (lane == 0) sc[wid] = wabs;
    __syncthreads();

    // finalize r
    float linv = 1.0f / sred[1];
    g_r[(size_t)b * DF + tid] = acc * linv;

    // feat scale = mean |f|
    if (tid == 0) {
        float t = 0.f;
        #pragma unroll
        for (int w = 0; w < 16; w++) t += sc[w];
        sred[2] = t * (1.0f / (float)(C_SZ * DF));
    }
    __syncthreads();
    const float scale = sred[2];

    // ---- fused gate MLP: warp w computes hidden units 2w, 2w+1 ----
    // h_pre = g1b[h] + sum_d Q[d]*g1w[h][d] + scale*g1w[h][512]
    #pragma unroll
    for (int cc = 0; cc < 2; cc++) {
        const int h = wid * 2 + cc;
        const float* wrow = g1w + (size_t)h * (DT + 1);
        float s = 0.f;
        #pragma unroll
        for (int k = 0; k < 16; k++)
            s = fmaf(Qs[lane + 32 * k], wrow[lane + 32 * k], s);
        #pragma unroll
        for (int o = 16; o; o >>= 1) s += __shfl_xor_sync(0xffffffffu, s, o);
        if (lane == 0) sc[h] = s + g1b[h] + scale * wrow[DT];
    }
    __syncthreads();

    if (wid == 0) {
        float h  = sc[lane];
        float ge = 0.5f * h * (1.0f + erff(h * 0.70710678118654752f));
        float y  = g2w[lane] * ge;
        #pragma unroll
        for (int o = 16; o; o >>= 1) y += __shfl_xor_sync(0xffffffffu, y, o);
        if (lane == 0) {
            float gate = 1.0f / (1.0f + expf(-(y + g2b[0])));
            g_gate[b]   = gate;
            gate_out[b] = gate;
        }
    }
}

// ---------------------------------------------------------------------------
// Kernel 3: out[b][t] = gate[b] * ( sum_f r[b][f]*Wv[t][f] + Wv_b[t] )
// NT GEMM. Tile 32b x 128t, K-step 32, 256 threads, f32x2 inner.
// Both operands K-contiguous -> LDG + transposed STS, reg-staged, double-buffered.
// ---------------------------------------------------------------------------
__global__ __launch_bounds__(256) void out_gemm(const float* __restrict__ Wv,
                                                const float* __restrict__ Wvb,
                                                float* __restrict__ out) {
    __shared__ float As[2][32 * 36];    // [f][b], stride 36
    __shared__ float Bs[2][32 * 132];   // [f][t], stride 132
    const int tid  = threadIdx.x;
    const int b0   = blockIdx.y * 32;
    const int t0   = blockIdx.x * 128;
    const int wq   = tid >> 5;
    const int lane = tid & 31;
    const int arow = tid >> 3;
    const int kc   = (tid & 7) * 4;

    unsigned long long acc[4][2] = {};

    float4 rA = *(const float4*)(g_r + (size_t)(b0 + arow) * DF + kc);
    float4 rB[4];
    #pragma unroll
    for (int p = 0; p < 4; p++)
        rB[p] = *(const float4*)(Wv + (size_t)(t0 + arow + 32 * p) * DF + kc);

    #pragma unroll 1
    for (int it = 0; it < 16; it++) {
        const int cur = it & 1;
        As[cur][(kc + 0) * 36 + arow] = rA.x;
        As[cur][(kc + 1) * 36 + arow] = rA.y;
        As[cur][(kc + 2) * 36 + arow] = rA.z;
        As[cur][(kc + 3) * 36 + arow] = rA.w;
        #pragma unroll
        for (int p = 0; p < 4; p++) {
            int tr = arow + 32 * p;
            Bs[cur][(kc + 0) * 132 + tr] = rB[p].x;
            Bs[cur][(kc + 1) * 132 + tr] = rB[p].y;
            Bs[cur][(kc + 2) * 132 + tr] = rB[p].z;
            Bs[cur][(kc + 3) * 132 + tr] = rB[p].w;
        }
        if (it < 15) {
            const int k0n = (it + 1) * 32;
            rA = *(const float4*)(g_r + (size_t)(b0 + arow) * DF + k0n + kc);
            #pragma unroll
            for (int p = 0; p < 4; p++)
                rB[p] = *(const float4*)(Wv + (size_t)(t0 + arow + 32 * p) * DF + k0n + kc);
        }
        __syncthreads();
        #pragma unroll
        for (int kk = 0; kk < 32; kk++) {
            float4 a4 = *(const float4*)(&As[cur][kk * 36 + wq * 4]);
            ulonglong2 w = *(const ulonglong2*)(&Bs[cur][kk * 132 + lane * 4]);
            unsigned long long a0 = pack2(a4.x), a1 = pack2(a4.y),
                               a2 = pack2(a4.z), a3 = pack2(a4.w);
            ffma2(acc[0][0], a0, w.x); ffma2(acc[0][1], a0, w.y);
            ffma2(acc[1][0], a1, w.x); ffma2(acc[1][1], a1, w.y);
            ffma2(acc[2][0], a2, w.x); ffma2(acc[2][1], a2, w.y);
            ffma2(acc[3][0], a3, w.x); ffma2(acc[3][1], a3, w.y);
        }
        __syncthreads();
    }

    float4 bias = *(const float4*)(Wvb + t0 + lane * 4);
    #pragma unroll
    for (int i = 0; i < 4; i++) {
        int bb = b0 + wq * 4 + i;
        float g = g_gate[bb];
        float4 v;
        v.x = g * (lo32(acc[i][0]) + bias.x);
        v.y = g * (hi32(acc[i][0]) + bias.y);
        v.z = g * (lo32(acc[i][1]) + bias.z);
        v.w = g * (hi32(acc[i][1]) + bias.w);
        *(float4*)(out + (size_t)bb * DT + t0 + lane * 4) = v;
    }
}

// ---------------------------------------------------------------------------
// Launch. Inputs: Q, features, Wk_w, Wk_b, Wv_w, Wv_b, g1_w, g1_b, g2_w, g2_b.
// Output: [gate*feat_read (1024x512), gate (1024)].
// Wk_b shifts all scores of a batch equally -> cancels in softmax.
// ---------------------------------------------------------------------------
extern "C" void kernel_launch(void* const* d_in, const int* in_sizes, int n_in,
                              void* d_out, int out_size) {
    const float* Q   = (const float*)d_in[0];
    const float* F   = (const float*)d_in[1];
    const float* Wk  = (const float*)d_in[2];
    const float* Wvw = (const float*)d_in[4];
    const float* Wvb = (const float*)d_in[5];
    const float* g1w = (const float*)d_in[6];
    const float* g1b = (const float*)d_in[7];
    const float* g2w = (const float*)d_in[8];
    const float* g2b = (const float*)d_in[9];
    float* out = (float*)d_out;

    const int attn_smem = (512 + 512 + 3 * 16 * DF + 16 + 32 + 8) * (int)sizeof(float); // ~102.6 KB
    cudaFuncSetAttribute(attn_kernel, cudaFuncAttributeMaxDynamicSharedMemorySize, attn_smem);

    qk_gemm<<<dim3(4, 32), 256>>>(Q, Wk);
    attn_kernel<<<B_SZ, 512, attn_smem>>>(F, Q, g1w, g1b, g2w, g2b, out + B_SZ * DT);
    out_gemm<<<dim3(4, 32), 256>>>(Wvw, Wvb, out);
}